// round 13
// baseline (speedup 1.0000x reference)
#include <cuda_runtime.h>

#define NB_EMAX  2048
#define NB_L     8
#define NB_HID   128
#define NB_TH    512
#define NB_QCAP  256   // frontier cap per level (expected peak ~16-32)

// ---------------------------------------------------------------------------
// One block per graph; fully independent blocks. Index-free design:
// each thread holds 4 edges of the batch in registers; walk frontiers are
// matched against them by broadcast compare — no adjacency structure at all.
//
// Walk item = (src_cur, dst_cur, start). Successor rule (B[cur,p]=1):
//   dst_p == src_cur && src_p != dst_cur.
// Expanding a depth-k item whose successor p == start closes a non-
// backtracking walk of length k+1 -> sigv[k] (= diag(B^{k+1})).
// ---------------------------------------------------------------------------
__global__ __launch_bounds__(NB_TH, 1)
void k_graph(const int* __restrict__ ei, const int* __restrict__ eg,
             const float* __restrict__ W1, const float* __restrict__ b1,
             const float* __restrict__ W2, const float* __restrict__ b2,
             float* __restrict__ out, int E) {
    __shared__ int2  s_qa[NB_QCAP];        // frontiers (ping-pong)
    __shared__ int2  s_qb[NB_QCAP];
    __shared__ int   s_n[NB_L + 1];        // per-depth item counters
    __shared__ int   s_sigv[NB_L];         // integer closed-walk counts
    __shared__ float s_part[4];

    const int g    = blockIdx.x;
    const int tid  = threadIdx.x;
    const int lane = tid & 31;
    const int warp = tid >> 5;

    // ---- 0: prefetch this thread's 4 edges + MLP weights into registers ----
    const int4* ei4 = (const int4*)ei;
    const int4* eg4 = (const int4*)eg;
    const int nq = E >> 2;                 // E = 2048 -> 512 (== NB_TH)
    const bool have = (tid < nq);
    int4 s4, d4, g4;
    if (have) {
        s4 = ei4[tid];
        d4 = ei4[nq + tid];
        g4 = eg4[tid];
    }
    float w[NB_L], b1v = 0.0f, w2v = 0.0f;
    if (tid < NB_HID) {
#pragma unroll
        for (int l = 0; l < NB_L; l++) w[l] = __ldg(&W1[l * NB_HID + tid]);
        b1v = __ldg(&b1[tid]);
        w2v = __ldg(&W2[tid]);
    }

    // ---- 1: init counters (overlaps load latency) ----
    if (tid < NB_L)     s_sigv[tid] = 0;
    if (tid < NB_L + 1) s_n[tid]    = 0;
    __syncthreads();

    // ---- 2: seed depth-0 frontier with this graph's edges ----
    int es[4], ed[4];
    if (have) {
        es[0] = s4.x; es[1] = s4.y; es[2] = s4.z; es[3] = s4.w;
        ed[0] = d4.x; ed[1] = d4.y; ed[2] = d4.z; ed[3] = d4.w;
        const int gi[4] = { g4.x, g4.y, g4.z, g4.w };
#pragma unroll
        for (int c = 0; c < 4; c++) {
            if (gi[c] == g) {
                int pos = atomicAdd(&s_n[0], 1);
                if (pos < NB_QCAP)
                    s_qa[pos] = make_int2((es[c] << 16) | ed[c], (tid << 2) | c);
            }
        }
    }

    // ---- 3: 8 broadcast-match expansion rounds ----
    // round k expands depth-k items; closures have length k+1 -> sigv[k].
    // k=0 closures are structurally impossible (need dst==src && src!=dst).
    const int myid = tid << 2;             // ids of this thread's edges
#pragma unroll
    for (int k = 0; k < NB_L; k++) {
        __syncthreads();                   // publish round k-1 (or seed)
        const int n = min(s_n[k], NB_QCAP);
        if (n == 0) break;                 // uniform: read after barrier
        if (have) {
            const int2* inq  = (k & 1) ? s_qb : s_qa;
            int2*       outq = (k & 1) ? s_qa : s_qb;
            const bool push = (k + 1 < NB_L);
            for (int it = 0; it < n; it++) {
                const int2 item = inq[it];        // broadcast LDS
                const int key   = item.x >> 16;   // src_cur
                const int forb  = item.x & 0xFFFF;// dst_cur
                const int start = item.y;
#pragma unroll
                for (int c = 0; c < 4; c++) {
                    if (ed[c] == key && es[c] != forb) {
                        if ((myid | c) == start) atomicAdd(&s_sigv[k], 1);
                        if (push) {
                            int pos = atomicAdd(&s_n[k + 1], 1);
                            if (pos < NB_QCAP)
                                outq[pos] = make_int2((es[c] << 16) | ed[c], start);
                        }
                    }
                }
            }
        }
    }
    __syncthreads();

    // ---- 4: MLP for this graph ----
    float v = 0.0f;
    if (tid < NB_HID) {
        float h = b1v;
#pragma unroll
        for (int l = 0; l < NB_L; l++)
            h = fmaf((float)s_sigv[l], w[l], h);
        v = fmaxf(h, 0.0f) * w2v;
    }
#pragma unroll
    for (int o = 16; o; o >>= 1) v += __shfl_xor_sync(0xffffffffu, v, o);
    if (tid < NB_HID && lane == 0) s_part[warp] = v;
    __syncthreads();
    if (tid == 0) {
        float tot = __ldg(&b2[0]);
#pragma unroll
        for (int ww = 0; ww < NB_HID / 32; ww++) tot += s_part[ww];
        out[g] = tot;
    }
}

extern "C" void kernel_launch(void* const* d_in, const int* in_sizes, int n_in,
                              void* d_out, int out_size) {
    const int*   ei = (const int*)  d_in[0];   // edge_index [2, E]
    const int*   eg = (const int*)  d_in[1];   // edge_graph [E]
    const float* W1 = (const float*)d_in[2];   // [L, HID]
    const float* b1 = (const float*)d_in[3];   // [HID]
    const float* W2 = (const float*)d_in[4];   // [HID, 1]
    const float* b2 = (const float*)d_in[5];   // [1]
    float* out = (float*)d_out;                // [G, 1]

    const int E = in_sizes[0] / 2;
    const int G = out_size;

    k_graph<<<G, NB_TH>>>(ei, eg, W1, b1, W2, b2, out, E);
}

// round 14
// speedup vs baseline: 1.7341x; 1.7341x over previous
#include <cuda_runtime.h>

#define NB_NODES 4096
#define NB_EMAX  2048
#define NB_L     8
#define NB_HID   128
#define NB_TH    512
#define NB_SMAX  256    // max start edges per graph (E/G = 16 expected)

// ---------------------------------------------------------------------------
// Fused chain entry: s_chain[p] = next(16b, 0xFFFF=null) | src_p << 16.
// Walking bucket `node` enumerates all edges p with dst_p == node; dst_p is
// implicit, so each step is a single LDS.
//
// walk<K>(node=src_cur, forb=dst_cur, start): iterates successors p (depth K)
// of the depth-(K-1) edge cur; rule dst_p == src_cur && src_p != dst_cur.
// p == start closes a non-backtracking walk of length K -> cnt[K-1]
// (= diag(B^K)). Fully inlined; all per-depth state in registers.
// ---------------------------------------------------------------------------
template<int K>
__device__ __forceinline__ void walk(const int* __restrict__ sh,
                                     const int* __restrict__ sc,
                                     int node, int forb, int start, int* cnt) {
    if constexpr (K <= NB_L) {
        int p = sh[node];
        while (p >= 0) {
            const int e   = sc[p];
            const int spn = e >> 16;        // src_p
            const int nxt = e & 0xFFFF;
            if (spn != forb) {              // not backtracking
                if (p == start) cnt[K - 1]++;
                walk<K + 1>(sh, sc, spn, node, start, cnt);
            }
            p = (nxt == 0xFFFF) ? -1 : nxt;
        }
    }
}

// ---------------------------------------------------------------------------
// One block per graph; fully independent blocks.
// ---------------------------------------------------------------------------
__global__ __launch_bounds__(NB_TH, 1)
void k_graph(const int* __restrict__ ei, const int* __restrict__ eg,
             const float* __restrict__ W1, const float* __restrict__ b1,
             const float* __restrict__ W2, const float* __restrict__ b2,
             float* __restrict__ out, int E) {
    __shared__ int   s_head[NB_NODES];     // 16 KB (int: shared atomicExch target)
    __shared__ int   s_chain[NB_EMAX];     //  8 KB  next(16b) | src(16b)
    __shared__ int2  s_starts[NB_SMAX];    //  2 KB  {edge id, src<<16|dst}
    __shared__ int   s_ns;
    __shared__ int   s_sigv[NB_L];         // integer closed-walk counts
    __shared__ float s_part[4];

    const int g    = blockIdx.x;
    const int tid  = threadIdx.x;
    const int lane = tid & 31;
    const int warp = tid >> 5;

    // ---- 0: PREFETCH global data into registers at kernel entry ----
    const int4* ei4 = (const int4*)ei;
    const int4* eg4 = (const int4*)eg;
    const int nq = E >> 2;                 // E = 2048 -> 512 (== NB_TH)
    int4 s4, d4, g4;
    const int t0 = tid;
    if (t0 < nq) {
        s4 = ei4[t0];
        d4 = ei4[nq + t0];
        g4 = eg4[t0];
    }
    float w[NB_L], b1v = 0.0f, w2v = 0.0f;
    if (tid < NB_HID) {
#pragma unroll
        for (int l = 0; l < NB_L; l++) w[l] = __ldg(&W1[l * NB_HID + tid]);
        b1v = __ldg(&b1[tid]);
        w2v = __ldg(&W2[tid]);
    }

    // ---- 1: init head (vectorized) / counters (overlaps prefetch latency) --
    {
        int4* h4 = (int4*)s_head;
        const int4 mv = make_int4(-1, -1, -1, -1);
#pragma unroll
        for (int v = tid; v < NB_NODES / 4; v += NB_TH) h4[v] = mv;
    }
    if (tid < NB_L) s_sigv[tid] = 0;
    if (tid == 0)  s_ns = 0;
    __syncthreads();

    // ---- 2: fused build + start collection (prefetched regs) --------------
    for (int t = t0; t < nq; t += NB_TH) {
        if (t != t0) { s4 = ei4[t]; d4 = ei4[nq + t]; g4 = eg4[t]; }
        const int j = t << 2;
        const int old0 = atomicExch(&s_head[d4.x], j + 0);
        const int old1 = atomicExch(&s_head[d4.y], j + 1);
        const int old2 = atomicExch(&s_head[d4.z], j + 2);
        const int old3 = atomicExch(&s_head[d4.w], j + 3);
        s_chain[j + 0] = (old0 & 0xFFFF) | (s4.x << 16);
        s_chain[j + 1] = (old1 & 0xFFFF) | (s4.y << 16);
        s_chain[j + 2] = (old2 & 0xFFFF) | (s4.z << 16);
        s_chain[j + 3] = (old3 & 0xFFFF) | (s4.w << 16);
        if (g4.x == g) { int p = atomicAdd(&s_ns, 1); if (p < NB_SMAX) s_starts[p] = make_int2(j + 0, (s4.x << 16) | d4.x); }
        if (g4.y == g) { int p = atomicAdd(&s_ns, 1); if (p < NB_SMAX) s_starts[p] = make_int2(j + 1, (s4.y << 16) | d4.y); }
        if (g4.z == g) { int p = atomicAdd(&s_ns, 1); if (p < NB_SMAX) s_starts[p] = make_int2(j + 2, (s4.z << 16) | d4.z); }
        if (g4.w == g) { int p = atomicAdd(&s_ns, 1); if (p < NB_SMAX) s_starts[p] = make_int2(j + 3, (s4.w << 16) | d4.w); }
    }
    __syncthreads();

    // ---- 3: warp-per-start DFS, lane-strided depth-1 children -------------
    // length-1 closure is structurally impossible (self-loop && non-self-loop).
    int cnt[NB_L];
#pragma unroll
    for (int k = 0; k < NB_L; k++) cnt[k] = 0;

    const int ns = min(s_ns, NB_SMAX);
    for (int si = warp; si < ns; si += NB_TH >> 5) {
        const int2 st  = s_starts[si];
        const int id   = st.x;
        const int isrc = st.y >> 16;
        const int idst = st.y & 0xFFFF;
        int idx = 0;
        int p = s_head[isrc];
        while (p >= 0) {
            const int e   = s_chain[p];
            const int spn = e >> 16;                    // src_p
            const int nxt = e & 0xFFFF;
            if (spn != idst) {                          // not backtracking
                if ((idx++ & 31) == lane)               // stride over lanes
                    walk<2>(s_head, s_chain, spn, isrc, id, cnt);
            }
            p = (nxt == 0xFFFF) ? -1 : nxt;
        }
    }
#pragma unroll
    for (int k = 1; k < NB_L; k++) {
        int v = cnt[k];
#pragma unroll
        for (int o = 16; o; o >>= 1) v += __shfl_xor_sync(0xffffffffu, v, o);
        if (lane == 0 && v) atomicAdd(&s_sigv[k], v);
    }
    __syncthreads();

    // ---- 4: MLP for this graph --------------------------------------------
    float v = 0.0f;
    if (tid < NB_HID) {
        float h = b1v;
#pragma unroll
        for (int l = 0; l < NB_L; l++)
            h = fmaf((float)s_sigv[l], w[l], h);
        v = fmaxf(h, 0.0f) * w2v;
    }
#pragma unroll
    for (int o = 16; o; o >>= 1) v += __shfl_xor_sync(0xffffffffu, v, o);
    if (tid < NB_HID && lane == 0) s_part[warp] = v;
    __syncthreads();
    if (tid == 0) {
        float tot = __ldg(&b2[0]);
#pragma unroll
        for (int ww = 0; ww < NB_HID / 32; ww++) tot += s_part[ww];
        out[g] = tot;
    }
}

extern "C" void kernel_launch(void* const* d_in, const int* in_sizes, int n_in,
                              void* d_out, int out_size) {
    const int*   ei = (const int*)  d_in[0];   // edge_index [2, E]
    const int*   eg = (const int*)  d_in[1];   // edge_graph [E]
    const float* W1 = (const float*)d_in[2];   // [L, HID]
    const float* b1 = (const float*)d_in[3];   // [HID]
    const float* W2 = (const float*)d_in[4];   // [HID, 1]
    const float* b2 = (const float*)d_in[5];   // [1]
    float* out = (float*)d_out;                // [G, 1]

    const int E = in_sizes[0] / 2;
    const int G = out_size;

    k_graph<<<G, NB_TH>>>(ei, eg, W1, b1, W2, b2, out, E);
}